// round 16
// baseline (speedup 1.0000x reference)
#include <cuda_runtime.h>
#include <math.h>

// Problem constants
#define T_STEPS 100
#define B_SZ    256
#define D_SZ    2048
#define M_TOTAL (T_STEPS * B_SZ)          // 25600
#define BD      (B_SZ * D_SZ)             // 524288

// Reference accumulation structure — identified by error spectroscopy over 7
// rounds (all diff counts 9/3/4/5/6/6/4 fit var model uniquely):
// EIGHT equal ascending fp32 FMA chains of 256 k each, joined SEQUENTIALLY
// by fp32 adds. KC_TILES = 256/16 = 16 BK-tiles per block.
#define KC_TILES 16

// Scratch for encoder output (allowed: __device__ global, no cudaMalloc)
__device__ float g_enc[(size_t)M_TOTAL * D_SZ];

// ---------------- packed f32x2 helpers (sm_103a FFMA2 path) ----------------
// fma.rn.f32x2 / add.rn.f32x2 = two independent IEEE fp32 ops (single rounding
// per lane) -> packed lane arithmetic is bit-identical to scalar in same order.
typedef unsigned long long u64;

__device__ __forceinline__ u64 pk2(float lo, float hi) {
    u64 r; asm("mov.b64 %0, {%1,%2};" : "=l"(r) : "f"(lo), "f"(hi)); return r;
}
__device__ __forceinline__ void upk2(u64 v, float& lo, float& hi) {
    asm("mov.b64 {%0,%1}, %2;" : "=f"(lo), "=f"(hi) : "l"(v));
}
__device__ __forceinline__ u64 fma2(u64 a, u64 b, u64 d) {
    u64 r; asm("fma.rn.f32x2 %0, %1, %2, %3;" : "=l"(r) : "l"(a), "l"(b), "l"(d)); return r;
}
__device__ __forceinline__ u64 add2(u64 a, u64 b) {
    u64 r; asm("add.rn.f32x2 %0, %1, %2;" : "=l"(r) : "l"(a), "l"(b)); return r;
}

// ---------------------------------------------------------------------------
// Tiled fp32 GEMM: C[M,N] = A[M,K] * W[N,K]^T (+ bias, optional sigmoid)
// BM=BN=128, BK=16, 256 threads, 8x8 per-thread microtile, double-buffered.
// Accumulation replicates the reference bitwise:
//   - 8 blocks of k=256, each an ascending single-accumulator FMA chain
//   - blocks joined sequentially into the running total by ONE fp32 add each
//   - then one fp32 bias add
// MODE 0: encoder — A gathered from x[B,C,T,H,W]; epilogue C = tot + bias
// MODE 1: decoder — A contiguous [M,K];  epilogue C = sigmoid(tot + bias)
// ---------------------------------------------------------------------------

__device__ __forceinline__ float4 loadA_enc(const float* __restrict__ x,
                                            int t, int b, int k) {
    int hw = k & 1023;
    int c  = k >> 10;
    // x index: ((b*2 + c)*100 + t)*1024 + hw
    return *(const float4*)(x + ((((b << 1) + c) * T_STEPS + t) << 10) + hw);
}

template <int MODE>
__global__ void __launch_bounds__(256, 1)
gemm_k(const float* __restrict__ A,      // MODE0: x ; MODE1: spk [M,K]
       const float* __restrict__ W,      // [N,K]
       const float* __restrict__ bias,   // [N]
       float* __restrict__ Cout)         // [M,N]
{
    const int K = D_SZ;
    __shared__ float As[2][16][132];
    __shared__ float Bs[2][16][132];

    const int tid = threadIdx.x;
    const int m0 = blockIdx.y * 128;
    const int n0 = blockIdx.x * 128;

    // Global-load mapping: thread -> (row = tid/4 and +64, 4 consecutive k)
    const int lr = tid >> 2;            // 0..63
    const int lc = (tid & 3) << 2;      // 0,4,8,12

    const int ma0 = m0 + lr;
    const int ma1 = m0 + lr + 64;
    const int nb0 = n0 + lr;
    const int nb1 = n0 + lr + 64;

    // Encoder gather decomposition (hoisted)
    const int ta0 = ma0 >> 8, ba0 = ma0 & 255;
    const int ta1 = ma1 >> 8, ba1 = ma1 & 255;

    const float* wrow0 = W + (size_t)nb0 * K;
    const float* wrow1 = W + (size_t)nb1 * K;

    // Compute mapping
    const int tx8 = (tid & 15) << 3;    // n offset within tile
    const int ty8 = (tid >> 4) << 3;    // m offset within tile

    u64 acc[8][4];   // current kc-block accumulator (ascending chain)
    u64 tot[8][4];   // running total across kc-blocks (one add per join)
#pragma unroll
    for (int i = 0; i < 8; i++)
#pragma unroll
        for (int j = 0; j < 4; j++) { acc[i][j] = 0ULL; tot[i][j] = 0ULL; }

    float4 ra0, ra1, rb0, rb1;

    // ---- prologue: load tile 0 ----
    {
        int k = lc;
        if (MODE == 0) {
            ra0 = loadA_enc(A, ta0, ba0, k);
            ra1 = loadA_enc(A, ta1, ba1, k);
        } else {
            ra0 = *(const float4*)(A + (size_t)ma0 * K + k);
            ra1 = *(const float4*)(A + (size_t)ma1 * K + k);
        }
        rb0 = *(const float4*)(wrow0 + k);
        rb1 = *(const float4*)(wrow1 + k);
    }
    As[0][lc + 0][lr] = ra0.x;  As[0][lc + 1][lr] = ra0.y;
    As[0][lc + 2][lr] = ra0.z;  As[0][lc + 3][lr] = ra0.w;
    As[0][lc + 0][lr + 64] = ra1.x;  As[0][lc + 1][lr + 64] = ra1.y;
    As[0][lc + 2][lr + 64] = ra1.z;  As[0][lc + 3][lr + 64] = ra1.w;
    Bs[0][lc + 0][lr] = rb0.x;  Bs[0][lc + 1][lr] = rb0.y;
    Bs[0][lc + 2][lr] = rb0.z;  Bs[0][lc + 3][lr] = rb0.w;
    Bs[0][lc + 0][lr + 64] = rb1.x;  Bs[0][lc + 1][lr + 64] = rb1.y;
    Bs[0][lc + 2][lr + 64] = rb1.z;  Bs[0][lc + 3][lr + 64] = rb1.w;

    int buf = 0;
    const int kIters = K / 16;          // 128 tiles; kc boundary every 16 tiles

    for (int kt = 0; kt < kIters; kt++) {
        __syncthreads();

        // issue global loads for next tile early (latency hiding)
        if (kt + 1 < kIters) {
            int k = ((kt + 1) << 4) + lc;
            if (MODE == 0) {
                ra0 = loadA_enc(A, ta0, ba0, k);
                ra1 = loadA_enc(A, ta1, ba1, k);
            } else {
                ra0 = *(const float4*)(A + (size_t)ma0 * K + k);
                ra1 = *(const float4*)(A + (size_t)ma1 * K + k);
            }
            rb0 = *(const float4*)(wrow0 + k);
            rb1 = *(const float4*)(wrow1 + k);
        }

        // compute on current buffer (FFMA2, k ascending within tile)
#pragma unroll
        for (int kk = 0; kk < 16; kk++) {
            float af[8], bf[8];
            *(float4*)&af[0] = *(const float4*)&As[buf][kk][ty8];
            *(float4*)&af[4] = *(const float4*)&As[buf][kk][ty8 + 4];
            *(float4*)&bf[0] = *(const float4*)&Bs[buf][kk][tx8];
            *(float4*)&bf[4] = *(const float4*)&Bs[buf][kk][tx8 + 4];

            u64 bp[4];
            bp[0] = pk2(bf[0], bf[1]);
            bp[1] = pk2(bf[2], bf[3]);
            bp[2] = pk2(bf[4], bf[5]);
            bp[3] = pk2(bf[6], bf[7]);
#pragma unroll
            for (int i = 0; i < 8; i++) {
                u64 ap = pk2(af[i], af[i]);
#pragma unroll
                for (int j = 0; j < 4; j++)
                    acc[i][j] = fma2(ap, bp[j], acc[i][j]);
            }
        }

        // kc-block boundary (every 256 k = 16 tiles): join block into total
        if (((kt + 1) & (KC_TILES - 1)) == 0 && (kt + 1) < kIters) {
#pragma unroll
            for (int i = 0; i < 8; i++)
#pragma unroll
                for (int j = 0; j < 4; j++) {
                    tot[i][j] = add2(tot[i][j], acc[i][j]);
                    acc[i][j] = 0ULL;
                }
        }

        // store staged tile into the other buffer
        if (kt + 1 < kIters) {
            buf ^= 1;
            As[buf][lc + 0][lr] = ra0.x;  As[buf][lc + 1][lr] = ra0.y;
            As[buf][lc + 2][lr] = ra0.z;  As[buf][lc + 3][lr] = ra0.w;
            As[buf][lc + 0][lr + 64] = ra1.x;  As[buf][lc + 1][lr + 64] = ra1.y;
            As[buf][lc + 2][lr + 64] = ra1.z;  As[buf][lc + 3][lr + 64] = ra1.w;
            Bs[buf][lc + 0][lr] = rb0.x;  Bs[buf][lc + 1][lr] = rb0.y;
            Bs[buf][lc + 2][lr] = rb0.z;  Bs[buf][lc + 3][lr] = rb0.w;
            Bs[buf][lc + 0][lr + 64] = rb1.x;  Bs[buf][lc + 1][lr + 64] = rb1.y;
            Bs[buf][lc + 2][lr + 64] = rb1.z;  Bs[buf][lc + 3][lr + 64] = rb1.w;
        }
    }

    // ---- epilogue: join 8th block, bias (+ sigmoid), stores ----
    float bv[8];
    *(float4*)&bv[0] = *(const float4*)(bias + n0 + tx8);
    *(float4*)&bv[4] = *(const float4*)(bias + n0 + tx8 + 4);

#pragma unroll
    for (int i = 0; i < 8; i++) {
        int m = m0 + ty8 + i;
        float* crow = Cout + (size_t)m * D_SZ + n0 + tx8;
        float r[8];
#pragma unroll
        for (int j = 0; j < 4; j++) {
            u64 fin = add2(tot[i][j], acc[i][j]);   // final (8th) block join
            float s0, s1;
            upk2(fin, s0, s1);
            float v0 = __fadd_rn(s0, bv[2 * j]);
            float v1 = __fadd_rn(s1, bv[2 * j + 1]);
            if (MODE == 1) {
                v0 = 1.0f / (1.0f + expf(-v0));
                v1 = 1.0f / (1.0f + expf(-v1));
            }
            r[2 * j]     = v0;
            r[2 * j + 1] = v1;
        }
        float4 v0, v1;
        v0.x = r[0]; v0.y = r[1]; v0.z = r[2]; v0.w = r[3];
        v1.x = r[4]; v1.y = r[5]; v1.z = r[6]; v1.w = r[7];
        *(float4*)(crow)     = v0;
        *(float4*)(crow + 4) = v1;
    }
}

// ---------------------------------------------------------------------------
// LIF scan: sequential over T, parallel over B*D neurons.
// (Scan rounding proven irrelevant to spikes — R1 vs R7 bit-identical.)
// ---------------------------------------------------------------------------
__global__ void __launch_bounds__(256)
lif_scan_k(const float* __restrict__ enc,
           const float* __restrict__ beta,
           float* __restrict__ spk_out)
{
    int idx = blockIdx.x * blockDim.x + threadIdx.x;   // 0..BD-1
    int d = idx & (D_SZ - 1);
    float bc = fminf(fmaxf(beta[d], 0.0f), 1.0f);

    float mem = 0.0f;
    float sp  = 0.0f;

    const float* ep = enc + idx;
    float* op = spk_out + idx;

#pragma unroll 4
    for (int t = 0; t < T_STEPS; t++) {
        mem = __fsub_rn(fmaf(bc, mem, ep[(size_t)t * BD]), sp);
        sp  = (mem > 1.0f) ? 1.0f : 0.0f;
        op[(size_t)t * BD] = sp;
    }
}

// ---------------------------------------------------------------------------
extern "C" void kernel_launch(void* const* d_in, const int* in_sizes, int n_in,
                              void* d_out, int out_size)
{
    const float* x     = (const float*)d_in[0];
    const float* W_enc = (const float*)d_in[1];
    const float* b_enc = (const float*)d_in[2];
    const float* W_dec = (const float*)d_in[3];
    const float* b_dec = (const float*)d_in[4];
    const float* beta  = (const float*)d_in[5];

    float* out = (float*)d_out;
    float* spk = out;                                   // [T,B,D]
    float* dec = out + (size_t)M_TOTAL * D_SZ;          // [T,B,D]

    float* enc = nullptr;
    cudaGetSymbolAddress((void**)&enc, g_enc);

    dim3 gemm_grid(D_SZ / 128, M_TOTAL / 128);          // (16, 200)

    // 1) encoder GEMM (fused gather + bias, 8x256 blocked chain) -> g_enc
    gemm_k<0><<<gemm_grid, 256>>>(x, W_enc, b_enc, enc);

    // 2) LIF scan -> spk (first half of d_out)
    lif_scan_k<<<BD / 256, 256>>>(enc, beta, spk);

    // 3) decoder GEMM (fused bias + sigmoid, same accumulation) -> dec
    gemm_k<1><<<gemm_grid, 256>>>(spk, W_dec, b_dec, dec);
}